// round 6
// baseline (speedup 1.0000x reference)
#include <cuda_runtime.h>
#include <cuda_bf16.h>

#define T_Q 4096
#define L_KV 4096
#define LPAD (L_KV + 32)
#define NQB 64
#define NCHUNK 2

typedef unsigned long long ull;

// ---------------- scratch ----------------
__device__ float g_V[2][LPAD][128];
__device__ float g_kraw[2][LPAD];
__device__ float g_alpha[2][T_Q];
__device__ float g_beta[2][T_Q];
__device__ int   g_a[2][T_Q];
__device__ int   g_e[2][T_Q];
__device__ int   g_nc[2][T_Q];
__device__ float g_pacc[NCHUNK][2][T_Q][128];
__device__ float g_pden[NCHUNK][2][T_Q];

// ---------------- helpers ----------------
__device__ __forceinline__ ull d_pk2(float a) {
    ull r; asm("mov.b64 %0, {%1, %1};" : "=l"(r) : "f"(a)); return r;
}
__device__ __forceinline__ ull d_fma2(ull a, ull b, ull c) {
    ull d; asm("fma.rn.f32x2 %0, %1, %2, %3;" : "=l"(d) : "l"(a), "l"(b), "l"(c)); return d;
}
__device__ __forceinline__ float2 d_up(ull v) {
    float2 f; asm("mov.b64 {%0, %1}, %2;" : "=f"(f.x), "=f"(f.y) : "l"(v)); return f;
}
__device__ __forceinline__ unsigned d_su32(const void* p) {
    unsigned r;
    asm("{ .reg .u64 t; cvta.to.shared.u64 t, %1; cvt.u32.u64 %0, t; }" : "=r"(r) : "l"(p));
    return r;
}

// ---------------- kernel 1: fused qparams + vproj ----------------
// blocks [0, NQB): per-query alpha/beta/ranges (64 queries each)
// blocks [NQB, NQB+256): V projection, 32 rows each; m = (b-NQB)>>7
__global__ void __launch_bounds__(256) k_pre(
    const float* __restrict__ ref_data, const float* __restrict__ ref_time,
    const int* __restrict__ ref_idx,
    const float* __restrict__ m1_data, const float* __restrict__ m1_time, const int* __restrict__ m1_idx,
    const float* __restrict__ m2_data, const float* __restrict__ m2_time, const int* __restrict__ m2_idx,
    const float* __restrict__ Wq, const float* __restrict__ bq,
    const float* __restrict__ Wk1, const float* __restrict__ bk1,
    const float* __restrict__ Wv1, const float* __restrict__ bv1,
    const float* __restrict__ Wk2, const float* __restrict__ bk2,
    const float* __restrict__ Wv2, const float* __restrict__ bv2)
{
    __shared__ __align__(16) float sm[64 * 130];
    int b = blockIdx.x;
    int tid = threadIdx.x;

    if (b < NQB) {
        // ---- qab path (unchanged from R5 pass) ----
        float* rbuf = sm;
        float* wA   = sm + 64 * 65;
        float* wB   = wA + 128;
        float* cAB  = wB + 128;
        int*   lb   = (int*)(cAB + 4);

        int t0 = b * 64;
        for (int i = tid; i < 64 * 64; i += 256) {
            int row = i >> 6, col = i & 63;
            rbuf[row * 65 + col] = ref_data[t0 * 64 + i];
        }

        if (tid < 128) {
            int m = tid >> 6, j = tid & 63;
            const float* Wk = m ? Wk2 : Wk1;
            const float* bk = m ? bk2 : bk1;
            const float* wqrow = Wq + j * 128;
            float aA = 0.f, aB = 0.f;
            #pragma unroll 4
            for (int i = 0; i < 127; i++) {
                float w = __ldg(wqrow + i + 1);
                aA += w * __ldg(bk + i);
                aB += w * __ldg(Wk + i);
            }
            wA[m * 64 + j] = __ldg(wqrow) - aA;
            wB[m * 64 + j] = aB;
        } else if (tid < 146) {
            int s = tid - 128, m = s / 9, g = s % 9;
            const int* midx = m ? m2_idx : m1_idx;
            int lo = 0, hi = L_KV;
            while (lo < hi) {
                int md = (lo + hi) >> 1;
                if (midx[md] < g) lo = md + 1; else hi = md;
            }
            lb[m * 9 + g] = lo;
        } else if (tid < 150) {
            int s = tid - 146;
            int m = s & 1; bool isB = s >= 2;
            const float* Wk = m ? Wk2 : Wk1;
            const float* bk = m ? bk2 : bk1;
            const float* vec = isB ? Wk : bk;
            float acc = 0.f;
            for (int i = 0; i < 127; i++) acc += __ldg(bq + i + 1) * __ldg(vec + i);
            cAB[s] = isB ? (acc + __ldg(Wk + 127)) : (__ldg(bq) - acc - __ldg(bk + 127));
        }
        __syncthreads();

        if (tid < 64) {
            int t = t0 + tid;
            float d0 = 0.f, d1 = 0.f, d2 = 0.f, d3 = 0.f;
            #pragma unroll 8
            for (int i = 0; i < 64; i++) {
                float r = rbuf[tid * 65 + i];
                d0 += r * wA[i];       d1 += r * wB[i];
                d2 += r * wA[64 + i];  d3 += r * wB[64 + i];
            }
            g_alpha[0][t] = d0 + cAB[0]; g_beta[0][t] = d1 + cAB[2];
            g_alpha[1][t] = d2 + cAB[1]; g_beta[1][t] = d3 + cAB[3];

            int id = ref_idx[t];
            float qt = ref_time[t];
            int lo1 = 0, hi1 = L_KV, lo2 = 0, hi2 = L_KV;
            #pragma unroll 1
            for (int it = 0; it < 13; it++) {
                if (lo1 < hi1) {
                    int md1 = (lo1 + hi1) >> 1;
                    if (m1_time[md1] <= qt) lo1 = md1 + 1; else hi1 = md1;
                }
                if (lo2 < hi2) {
                    int md2 = (lo2 + hi2) >> 1;
                    if (m2_time[md2] <= qt) lo2 = md2 + 1; else hi2 = md2;
                }
            }
            {
                int a = lb[id], bb = lb[id + 1];
                if (a == bb) { a = 0; bb = L_KV; }
                int e = min(bb, max(lo1, a));
                g_a[0][t] = a; g_e[0][t] = e; g_nc[0][t] = bb - e;
            }
            {
                int a = lb[9 + id], bb = lb[9 + id + 1];
                if (a == bb) { a = 0; bb = L_KV; }
                int e = min(bb, max(lo2, a));
                g_a[1][t] = a; g_e[1][t] = e; g_nc[1][t] = bb - e;
            }
        }
        return;
    }

    // ---- vproj path: 32 rows per CTA, warp owns 4 rows, float4 smem reads ----
    int vb = b - NQB;            // 0..255
    int m = vb >> 7;             // 0: m1, 1: m2
    int rb = vb & 127;           // row-block of 32
    int stride = m ? 66 : 130;
    int SST    = m ? 68 : 132;   // padded smem row stride (16B-aligned)
    int K      = m ? 64 : 128;
    const float* src = (m ? m2_data : m1_data) + rb * 32 * stride;

    {   // coalesced per-warp row staging into padded smem
        int w = tid >> 5, lane = tid & 31;
        for (int r = w; r < 32; r += 8)
            for (int c = lane; c < stride; c += 32)
                sm[r * SST + c] = src[r * stride + c];
    }

    if (vb == 0) {   // zero V/kraw padding once (visible to k_attn after kernel boundary)
        float* gv = &g_V[0][0][0];
        for (int i = tid; i < 2 * 32 * 128; i += 256) {
            int mm = i / (32 * 128);
            int r  = i - mm * 32 * 128;
            gv[(mm * LPAD + L_KV) * 128 + r] = 0.f;
        }
        if (tid < 64) g_kraw[tid >> 5][L_KV + (tid & 31)] = 0.f;
    }
    __syncthreads();

    int w = tid >> 5, lane = tid & 31;
    const ulonglong2* Wvp = (const ulonglong2*)(m ? Wv2 : Wv1);
    float4 bias = ((const float4*)(m ? bv2 : bv1))[lane];
    const float* rbase = sm + (w * 4) * SST;

    ull acc0[4], acc1[4];
    #pragma unroll
    for (int q = 0; q < 4; q++) { acc0[q] = 0ull; acc1[q] = 0ull; }

    int ng = K >> 2;
    for (int i4 = 0; i4 < ng; i4++) {
        float4 rq[4];
        #pragma unroll
        for (int q = 0; q < 4; q++)
            rq[q] = *(const float4*)(rbase + q * SST + i4 * 4);
        #pragma unroll
        for (int ii = 0; ii < 4; ii++) {
            ulonglong2 wv = Wvp[(i4 * 4 + ii) * 32 + lane];
            #pragma unroll
            for (int q = 0; q < 4; q++) {
                float rs = (ii == 0) ? rq[q].x : (ii == 1) ? rq[q].y : (ii == 2) ? rq[q].z : rq[q].w;
                ull rv = d_pk2(rs);
                acc0[q] = d_fma2(rv, wv.x, acc0[q]);
                acc1[q] = d_fma2(rv, wv.y, acc1[q]);
            }
        }
    }

    int r0 = rb * 32 + w * 4;
    #pragma unroll
    for (int q = 0; q < 4; q++) {
        float2 lo = d_up(acc0[q]), hi = d_up(acc1[q]);
        float4 o = make_float4(lo.x + bias.x, lo.y + bias.y, hi.x + bias.z, hi.y + bias.w);
        ((float4*)g_V[m][r0 + q])[lane] = o;
    }
    if (lane < 4) g_kraw[m][r0 + lane] = sm[(w * 4 + lane) * SST + stride - 1];
}

// ---------------- kernel 2: attention (unchanged from R5 pass) ----------------
__global__ void __launch_bounds__(128) k_attn(const float* __restrict__ lt1,
                                              const float* __restrict__ lt2)
{
    int m = blockIdx.y, ch = blockIdx.z;
    int c = blockIdx.x;                              // 0..127
    int qb = (c & 1) ? (127 - (c >> 1)) : (c >> 1);  // front/back pairing for balance
    int tid = threadIdx.x;
    int warp = tid >> 5, lane = tid & 31;
    int t0c = qb * 32;

    __shared__ __align__(16) float buf[2][32 * 128];   // 32 KB
    __shared__ __align__(16) ull wsm[4][8][32];        // 8 KB
    __shared__ int s_c0[32], s_c1[32], s_b[2];

    if (tid < 32) {
        int t = t0c + tid;
        int a = g_a[m][t], e = g_e[m][t];
        int len = e - a;
        int c0 = a + ((len * ch) >> 1);
        int c1 = a + ((len * (ch + 1)) >> 1);
        s_c0[tid] = c0; s_c1[tid] = c1;
        int rmin = (c1 > c0) ? c0 : 0x7fffffff;
        int rmax = (c1 > c0) ? c1 : 0;
        #pragma unroll
        for (int off = 16; off; off >>= 1) {
            rmin = min(rmin, __shfl_xor_sync(0xffffffffu, rmin, off));
            rmax = max(rmax, __shfl_xor_sync(0xffffffffu, rmax, off));
        }
        if (tid == 0) { s_b[0] = rmin; s_b[1] = rmax; }
    }
    __syncthreads();
    int amin = s_b[0], emax = s_b[1];

    float nitau = -__expf(-(m ? *lt2 : *lt1));       // -1/tau
    int t0 = t0c + warp * 8;

    float alpha[8], nbeta[8], dpart[8];
    int aq[8], eq[8];
    ull alo[8], ahi[8];
    #pragma unroll
    for (int q = 0; q < 8; q++) {
        int t = t0 + q;
        alpha[q] = g_alpha[m][t]; nbeta[q] = -g_beta[m][t];
        aq[q] = s_c0[warp * 8 + q]; eq[q] = s_c1[warp * 8 + q];
        dpart[q] = 0.f; alo[q] = 0ull; ahi[q] = 0ull;
    }

    const float* gV = &g_V[m][0][0];
    const float* kr = g_kraw[m];
    ull* wme = &wsm[warp][0][0];
    unsigned sbuf0 = d_su32(&buf[0][0]);
    unsigned sbuf1 = d_su32(&buf[1][0]);

    int ntiles = (emax > amin) ? ((emax - amin + 31) >> 5) : 0;

    if (ntiles > 0) {
        {
            const float* g = gV + (size_t)amin * 128;
            #pragma unroll
            for (int i = 0; i < 8; i++) {
                int cid = i * 128 + tid;
                asm volatile("cp.async.cg.shared.global [%0], [%1], 16;"
                             :: "r"(sbuf0 + cid * 16), "l"(g + cid * 4) : "memory");
            }
            asm volatile("cp.async.commit_group;" ::: "memory");
        }
        int p = 0;
        for (int it = 0; it < ntiles; it++) {
            int l0 = amin + it * 32;
            asm volatile("cp.async.wait_group 0;" ::: "memory");
            __syncthreads();
            if (it + 1 < ntiles) {
                const float* g = gV + (size_t)(l0 + 32) * 128;
                unsigned sd = p ? sbuf0 : sbuf1;
                #pragma unroll
                for (int i = 0; i < 8; i++) {
                    int cid = i * 128 + tid;
                    asm volatile("cp.async.cg.shared.global [%0], [%1], 16;"
                                 :: "r"(sd + cid * 16), "l"(g + cid * 4) : "memory");
                }
            }
            asm volatile("cp.async.commit_group;" ::: "memory");

            int l = l0 + lane;
            float k = __ldg(kr + l);
            #pragma unroll
            for (int q = 0; q < 8; q++) {
                float s = fmaf(nbeta[q], k, alpha[q]);
                float w = (l >= aq[q] && l < eq[q]) ? __expf(s * s * nitau) : 0.f;
                wme[q * 32 + lane] = d_pk2(w);
                dpart[q] += w;
            }
            __syncwarp();

            const ulonglong2* bp = (const ulonglong2*)buf[p];
            #pragma unroll 8
            for (int j = 0; j < 32; j++) {
                ulonglong2 v = bp[j * 32 + lane];
                #pragma unroll
                for (int q = 0; q < 8; q++) {
                    ull wq = wme[q * 32 + j];
                    alo[q] = d_fma2(wq, v.x, alo[q]);
                    ahi[q] = d_fma2(wq, v.y, ahi[q]);
                }
            }
            p ^= 1;
        }
    }

    #pragma unroll
    for (int q = 0; q < 8; q++)
        #pragma unroll
        for (int off = 16; off; off >>= 1)
            dpart[q] += __shfl_xor_sync(0xffffffffu, dpart[q], off);

    float4* pa = (float4*)g_pacc[ch][m];
    #pragma unroll
    for (int q = 0; q < 8; q++) {
        float2 lo = d_up(alo[q]), hi = d_up(ahi[q]);
        pa[(t0 + q) * 32 + lane] = make_float4(lo.x, lo.y, hi.x, hi.y);
        if (lane == 0) g_pden[ch][m][t0 + q] = dpart[q];
    }
}

// ---------------- kernel 3: combine chunks + normalize ----------------
__global__ void __launch_bounds__(256) k_norm(float* __restrict__ out)
{
    int idx = blockIdx.x * 256 + threadIdx.x;        // 0 .. 2*4096*32-1
    int m = idx >> 17;
    int r = idx & 131071;
    int t = r >> 5, lane = r & 31;

    float4 a0 = ((const float4*)g_pacc[0][m])[t * 32 + lane];
    float4 a1 = ((const float4*)g_pacc[1][m])[t * 32 + lane];
    float den = g_pden[0][m][t] + g_pden[1][m][t] + (float)g_nc[m][t];
    float inv = 1.f / den;
    ((float4*)out)[t * 64 + m * 32 + lane] =
        make_float4((a0.x + a1.x) * inv, (a0.y + a1.y) * inv,
                    (a0.z + a1.z) * inv, (a0.w + a1.w) * inv);
}

// ---------------- launch ----------------
extern "C" void kernel_launch(void* const* d_in, const int* in_sizes, int n_in,
                              void* d_out, int out_size)
{
    int RD, RT, RI, M1D, M1T, M1I, M2D, M2T, M2I, WQ, BQ, WK1, BK1, WV1, BV1, WK2, BK2, WV2, BV2, LT1, LT2;
    if (in_sizes[3] == 4096 * 130) {
        RD=0; RT=1; RI=2; M1D=3; M1T=4; M1I=5; M2D=6; M2T=7; M2I=8;
        WQ=9; BQ=10; WK1=11; BK1=12; WV1=13; BV1=14; WK2=15; BK2=16; WV2=17; BV2=18; LT1=19; LT2=20;
    } else {
        RD=0; RT=1; M1D=2; M1T=3; M2D=4; M2T=5;
        WQ=6; BQ=7; WK1=8; BK1=9; WV1=10; BV1=11; WK2=12; BK2=13; WV2=14; BV2=15;
        LT1=16; LT2=17; RI=18; M1I=19; M2I=20;
    }

    k_pre<<<NQB + 256, 256>>>(
        (const float*)d_in[RD], (const float*)d_in[RT], (const int*)d_in[RI],
        (const float*)d_in[M1D], (const float*)d_in[M1T], (const int*)d_in[M1I],
        (const float*)d_in[M2D], (const float*)d_in[M2T], (const int*)d_in[M2I],
        (const float*)d_in[WQ], (const float*)d_in[BQ],
        (const float*)d_in[WK1], (const float*)d_in[BK1],
        (const float*)d_in[WV1], (const float*)d_in[BV1],
        (const float*)d_in[WK2], (const float*)d_in[BK2],
        (const float*)d_in[WV2], (const float*)d_in[BV2]);

    k_attn<<<dim3(128, 2, NCHUNK), 128>>>(
        (const float*)d_in[LT1], (const float*)d_in[LT2]);

    k_norm<<<(2 * T_Q * 32) / 256, 256>>>((float*)d_out);
}

// round 7
// speedup vs baseline: 1.0251x; 1.0251x over previous
#include <cuda_runtime.h>
#include <cuda_bf16.h>

#define T_Q 4096
#define L_KV 4096
#define LPAD (L_KV + 32)
#define NQB 64
#define NCHUNK 2

typedef unsigned long long ull;

// ---------------- scratch ----------------
__device__ float g_V[2][LPAD][128];
__device__ float g_kraw[2][LPAD];
__device__ float g_alpha[2][T_Q];
__device__ float g_beta[2][T_Q];
__device__ int   g_a[2][T_Q];
__device__ int   g_e[2][T_Q];
__device__ int   g_nc[2][T_Q];
__device__ float g_pacc[NCHUNK][2][T_Q][128];
__device__ float g_pden[NCHUNK][2][T_Q];
__device__ float g_wA[2][64];
__device__ float g_wB[2][64];
__device__ float g_cAB[4];          // cA0 cA1 cB0 cB1
__device__ int   g_lb[2][9];

// ---------------- helpers ----------------
__device__ __forceinline__ ull d_pk2(float a) {
    ull r; asm("mov.b64 %0, {%1, %1};" : "=l"(r) : "f"(a)); return r;
}
__device__ __forceinline__ ull d_fma2(ull a, ull b, ull c) {
    ull d; asm("fma.rn.f32x2 %0, %1, %2, %3;" : "=l"(d) : "l"(a), "l"(b), "l"(c)); return d;
}
__device__ __forceinline__ float2 d_up(ull v) {
    float2 f; asm("mov.b64 {%0, %1}, %2;" : "=f"(f.x), "=f"(f.y) : "l"(v)); return f;
}
__device__ __forceinline__ unsigned d_su32(const void* p) {
    unsigned r;
    asm("{ .reg .u64 t; cvta.to.shared.u64 t, %1; cvt.u32.u64 %0, t; }" : "=r"(r) : "l"(p));
    return r;
}

// ---------------- kernel 0: shared setup (wA/wB/cAB/lb), computed once ----------------
// blocks 0..15: 8 warps each, warp gw = (m,j) computes wA[m][j], wB[m][j] by lane-split reduce
// block 16: threads 0-3 -> cAB, threads 4-21 -> idx lower bounds
__global__ void __launch_bounds__(256) k_setup(
    const float* __restrict__ Wq, const float* __restrict__ bq,
    const float* __restrict__ Wk1, const float* __restrict__ bk1,
    const float* __restrict__ Wk2, const float* __restrict__ bk2,
    const int* __restrict__ m1_idx, const int* __restrict__ m2_idx)
{
    int b = blockIdx.x;
    if (b < 16) {
        int warp = threadIdx.x >> 5, lane = threadIdx.x & 31;
        int gw = b * 8 + warp;            // 0..127
        int m = gw >> 6, j = gw & 63;
        const float* Wk = m ? Wk2 : Wk1;
        const float* bk = m ? bk2 : bk1;
        const float* wqrow = Wq + j * 128;
        float aA = 0.f, aB = 0.f;
        #pragma unroll
        for (int k = 0; k < 4; k++) {
            int i = lane + 32 * k;
            if (i < 127) {
                float w = __ldg(wqrow + i + 1);
                aA += w * __ldg(bk + i);
                aB += w * __ldg(Wk + i);
            }
        }
        #pragma unroll
        for (int off = 16; off; off >>= 1) {
            aA += __shfl_xor_sync(0xffffffffu, aA, off);
            aB += __shfl_xor_sync(0xffffffffu, aB, off);
        }
        if (lane == 0) {
            g_wA[m][j] = __ldg(wqrow) - aA;
            g_wB[m][j] = aB;
        }
    } else {
        int tid = threadIdx.x;
        if (tid < 4) {
            int m = tid & 1; bool isB = tid >= 2;
            const float* Wk = m ? Wk2 : Wk1;
            const float* bk = m ? bk2 : bk1;
            const float* vec = isB ? Wk : bk;
            float acc = 0.f;
            for (int i = 0; i < 127; i++) acc += __ldg(bq + i + 1) * __ldg(vec + i);
            g_cAB[tid] = isB ? (acc + __ldg(Wk + 127)) : (__ldg(bq) - acc - __ldg(bk + 127));
        } else if (tid < 22) {
            int s = tid - 4, m = s / 9, g = s % 9;
            const int* midx = m ? m2_idx : m1_idx;
            int lo = 0, hi = L_KV;
            while (lo < hi) {
                int md = (lo + hi) >> 1;
                if (midx[md] < g) lo = md + 1; else hi = md;
            }
            g_lb[m][g] = lo;
        }
    }
}

// ---------------- templated vproj core ----------------
template<int K, int SST>
__device__ __forceinline__ void vproj_core(const float* __restrict__ sm, int tid, int m, int rb,
                                           const float* __restrict__ Wv, const float* __restrict__ bv)
{
    int w = tid >> 5, lane = tid & 31;
    const ulonglong2* Wvp = (const ulonglong2*)Wv;
    float4 bias = ((const float4*)bv)[lane];
    const float* rbase = sm + (w * 4) * SST;

    ull acc0[4], acc1[4];
    #pragma unroll
    for (int q = 0; q < 4; q++) { acc0[q] = 0ull; acc1[q] = 0ull; }

    #pragma unroll 4
    for (int i4 = 0; i4 < K / 4; i4++) {
        float4 rq[4];
        #pragma unroll
        for (int q = 0; q < 4; q++)
            rq[q] = *(const float4*)(rbase + q * SST + i4 * 4);
        #pragma unroll
        for (int ii = 0; ii < 4; ii++) {
            ulonglong2 wv = Wvp[(i4 * 4 + ii) * 32 + lane];
            #pragma unroll
            for (int q = 0; q < 4; q++) {
                float rs = (ii == 0) ? rq[q].x : (ii == 1) ? rq[q].y : (ii == 2) ? rq[q].z : rq[q].w;
                ull rv = d_pk2(rs);
                acc0[q] = d_fma2(rv, wv.x, acc0[q]);
                acc1[q] = d_fma2(rv, wv.y, acc1[q]);
            }
        }
    }

    int r0 = rb * 32 + w * 4;
    #pragma unroll
    for (int q = 0; q < 4; q++) {
        float2 lo = d_up(acc0[q]), hi = d_up(acc1[q]);
        float4 o = make_float4(lo.x + bias.x, lo.y + bias.y, hi.x + bias.z, hi.y + bias.w);
        ((float4*)g_V[m][r0 + q])[lane] = o;
    }
    if (lane < 4) g_kraw[m][r0 + lane] = sm[(w * 4 + lane) * SST + (K + 2) - 1];
}

// ---------------- kernel 1: qparams (light) + vproj ----------------
// blocks [0, NQB): 64 queries each — dots vs precomputed wA/wB + binary searches
// blocks [NQB, NQB+256): V projection, 32 rows each; m = (b-NQB)>>7
__global__ void __launch_bounds__(256) k_pre(
    const float* __restrict__ ref_data, const float* __restrict__ ref_time,
    const int* __restrict__ ref_idx,
    const float* __restrict__ m1_data, const float* __restrict__ m1_time,
    const float* __restrict__ m2_data, const float* __restrict__ m2_time,
    const float* __restrict__ Wv1, const float* __restrict__ bv1,
    const float* __restrict__ Wv2, const float* __restrict__ bv2)
{
    __shared__ __align__(16) float sm[64 * 132];
    int b = blockIdx.x;
    int tid = threadIdx.x;

    if (b < NQB) {
        // ---- qab path (light) ----
        float* rbuf = sm;                 // [64][65]
        int t0 = b * 64;
        for (int i = tid; i < 64 * 64; i += 256) {
            int row = i >> 6, col = i & 63;
            rbuf[row * 65 + col] = ref_data[t0 * 64 + i];
        }
        __syncthreads();

        if (tid < 64) {
            int t = t0 + tid;
            float d0 = 0.f, d1 = 0.f, d2 = 0.f, d3 = 0.f;
            #pragma unroll 8
            for (int i = 0; i < 64; i++) {
                float r = rbuf[tid * 65 + i];
                d0 += r * g_wA[0][i];  d1 += r * g_wB[0][i];
                d2 += r * g_wA[1][i];  d3 += r * g_wB[1][i];
            }
            g_alpha[0][t] = d0 + g_cAB[0]; g_beta[0][t] = d1 + g_cAB[2];
            g_alpha[1][t] = d2 + g_cAB[1]; g_beta[1][t] = d3 + g_cAB[3];

            int id = ref_idx[t];
            float qt = ref_time[t];
            int lo1 = 0, hi1 = L_KV, lo2 = 0, hi2 = L_KV;
            #pragma unroll 1
            for (int it = 0; it < 13; it++) {
                if (lo1 < hi1) {
                    int md1 = (lo1 + hi1) >> 1;
                    if (m1_time[md1] <= qt) lo1 = md1 + 1; else hi1 = md1;
                }
                if (lo2 < hi2) {
                    int md2 = (lo2 + hi2) >> 1;
                    if (m2_time[md2] <= qt) lo2 = md2 + 1; else hi2 = md2;
                }
            }
            {
                int a = g_lb[0][id], bb = g_lb[0][id + 1];
                if (a == bb) { a = 0; bb = L_KV; }
                int e = min(bb, max(lo1, a));
                g_a[0][t] = a; g_e[0][t] = e; g_nc[0][t] = bb - e;
            }
            {
                int a = g_lb[1][id], bb = g_lb[1][id + 1];
                if (a == bb) { a = 0; bb = L_KV; }
                int e = min(bb, max(lo2, a));
                g_a[1][t] = a; g_e[1][t] = e; g_nc[1][t] = bb - e;
            }
        }
        return;
    }

    // ---- vproj path: 32 rows per CTA ----
    int vb = b - NQB;            // 0..255
    int m = vb >> 7;             // 0: m1, 1: m2
    int rb = vb & 127;           // row-block of 32
    int stride = m ? 66 : 130;
    int SST    = m ? 68 : 132;   // padded smem row stride (16B-aligned)
    const float* src = (m ? m2_data : m1_data) + rb * 32 * stride;

    {   // coalesced per-warp row staging into padded smem
        int w = tid >> 5, lane = tid & 31;
        for (int r = w; r < 32; r += 8)
            for (int c = lane; c < stride; c += 32)
                sm[r * SST + c] = src[r * stride + c];
    }

    if (vb == 0) {   // zero V/kraw padding once
        float* gv = &g_V[0][0][0];
        for (int i = tid; i < 2 * 32 * 128; i += 256) {
            int mm = i / (32 * 128);
            int r  = i - mm * 32 * 128;
            gv[(mm * LPAD + L_KV) * 128 + r] = 0.f;
        }
        if (tid < 64) g_kraw[tid >> 5][L_KV + (tid & 31)] = 0.f;
    }
    __syncthreads();

    if (m == 0) vproj_core<128, 132>(sm, tid, 0, rb, Wv1, bv1);
    else        vproj_core<64,  68>(sm, tid, 1, rb, Wv2, bv2);
}

// ---------------- kernel 2: attention (unchanged, proven) ----------------
__global__ void __launch_bounds__(128) k_attn(const float* __restrict__ lt1,
                                              const float* __restrict__ lt2)
{
    int m = blockIdx.y, ch = blockIdx.z;
    int c = blockIdx.x;                              // 0..127
    int qb = (c & 1) ? (127 - (c >> 1)) : (c >> 1);  // front/back pairing for balance
    int tid = threadIdx.x;
    int warp = tid >> 5, lane = tid & 31;
    int t0c = qb * 32;

    __shared__ __align__(16) float buf[2][32 * 128];   // 32 KB
    __shared__ __align__(16) ull wsm[4][8][32];        // 8 KB
    __shared__ int s_c0[32], s_c1[32], s_b[2];

    if (tid < 32) {
        int t = t0c + tid;
        int a = g_a[m][t], e = g_e[m][t];
        int len = e - a;
        int c0 = a + ((len * ch) >> 1);
        int c1 = a + ((len * (ch + 1)) >> 1);
        s_c0[tid] = c0; s_c1[tid] = c1;
        int rmin = (c1 > c0) ? c0 : 0x7fffffff;
        int rmax = (c1 > c0) ? c1 : 0;
        #pragma unroll
        for (int off = 16; off; off >>= 1) {
            rmin = min(rmin, __shfl_xor_sync(0xffffffffu, rmin, off));
            rmax = max(rmax, __shfl_xor_sync(0xffffffffu, rmax, off));
        }
        if (tid == 0) { s_b[0] = rmin; s_b[1] = rmax; }
    }
    __syncthreads();
    int amin = s_b[0], emax = s_b[1];

    float nitau = -__expf(-(m ? *lt2 : *lt1));       // -1/tau
    int t0 = t0c + warp * 8;

    float alpha[8], nbeta[8], dpart[8];
    int aq[8], eq[8];
    ull alo[8], ahi[8];
    #pragma unroll
    for (int q = 0; q < 8; q++) {
        int t = t0 + q;
        alpha[q] = g_alpha[m][t]; nbeta[q] = -g_beta[m][t];
        aq[q] = s_c0[warp * 8 + q]; eq[q] = s_c1[warp * 8 + q];
        dpart[q] = 0.f; alo[q] = 0ull; ahi[q] = 0ull;
    }

    const float* gV = &g_V[m][0][0];
    const float* kr = g_kraw[m];
    ull* wme = &wsm[warp][0][0];
    unsigned sbuf0 = d_su32(&buf[0][0]);
    unsigned sbuf1 = d_su32(&buf[1][0]);

    int ntiles = (emax > amin) ? ((emax - amin + 31) >> 5) : 0;

    if (ntiles > 0) {
        {
            const float* g = gV + (size_t)amin * 128;
            #pragma unroll
            for (int i = 0; i < 8; i++) {
                int cid = i * 128 + tid;
                asm volatile("cp.async.cg.shared.global [%0], [%1], 16;"
                             :: "r"(sbuf0 + cid * 16), "l"(g + cid * 4) : "memory");
            }
            asm volatile("cp.async.commit_group;" ::: "memory");
        }
        int p = 0;
        for (int it = 0; it < ntiles; it++) {
            int l0 = amin + it * 32;
            asm volatile("cp.async.wait_group 0;" ::: "memory");
            __syncthreads();
            if (it + 1 < ntiles) {
                const float* g = gV + (size_t)(l0 + 32) * 128;
                unsigned sd = p ? sbuf0 : sbuf1;
                #pragma unroll
                for (int i = 0; i < 8; i++) {
                    int cid = i * 128 + tid;
                    asm volatile("cp.async.cg.shared.global [%0], [%1], 16;"
                                 :: "r"(sd + cid * 16), "l"(g + cid * 4) : "memory");
                }
            }
            asm volatile("cp.async.commit_group;" ::: "memory");

            int l = l0 + lane;
            float k = __ldg(kr + l);
            #pragma unroll
            for (int q = 0; q < 8; q++) {
                float s = fmaf(nbeta[q], k, alpha[q]);
                float w = (l >= aq[q] && l < eq[q]) ? __expf(s * s * nitau) : 0.f;
                wme[q * 32 + lane] = d_pk2(w);
                dpart[q] += w;
            }
            __syncwarp();

            const ulonglong2* bp = (const ulonglong2*)buf[p];
            #pragma unroll 8
            for (int j = 0; j < 32; j++) {
                ulonglong2 v = bp[j * 32 + lane];
                #pragma unroll
                for (int q = 0; q < 8; q++) {
                    ull wq = wme[q * 32 + j];
                    alo[q] = d_fma2(wq, v.x, alo[q]);
                    ahi[q] = d_fma2(wq, v.y, ahi[q]);
                }
            }
            p ^= 1;
        }
    }

    #pragma unroll
    for (int q = 0; q < 8; q++)
        #pragma unroll
        for (int off = 16; off; off >>= 1)
            dpart[q] += __shfl_xor_sync(0xffffffffu, dpart[q], off);

    float4* pa = (float4*)g_pacc[ch][m];
    #pragma unroll
    for (int q = 0; q < 8; q++) {
        float2 lo = d_up(alo[q]), hi = d_up(ahi[q]);
        pa[(t0 + q) * 32 + lane] = make_float4(lo.x, lo.y, hi.x, hi.y);
        if (lane == 0) g_pden[ch][m][t0 + q] = dpart[q];
    }
}

// ---------------- kernel 3: combine chunks + normalize ----------------
__global__ void __launch_bounds__(256) k_norm(float* __restrict__ out)
{
    int idx = blockIdx.x * 256 + threadIdx.x;        // 0 .. 2*4096*32-1
    int m = idx >> 17;
    int r = idx & 131071;
    int t = r >> 5, lane = r & 31;

    float4 a0 = ((const float4*)g_pacc[0][m])[t * 32 + lane];
    float4 a1 = ((const float4*)g_pacc[1][m])[t * 32 + lane];
    float den = g_pden[0][m][t] + g_pden[1][m][t] + (float)g_nc[m][t];
    float inv = 1.f / den;
    ((float4*)out)[t * 64 + m * 32 + lane] =
        make_float4((a0.x + a1.x) * inv, (a0.y + a1.y) * inv,
                    (a0.z + a1.z) * inv, (a0.w + a1.w) * inv);
}

// ---------------- launch ----------------
extern "C" void kernel_launch(void* const* d_in, const int* in_sizes, int n_in,
                              void* d_out, int out_size)
{
    int RD, RT, RI, M1D, M1T, M1I, M2D, M2T, M2I, WQ, BQ, WK1, BK1, WV1, BV1, WK2, BK2, WV2, BV2, LT1, LT2;
    if (in_sizes[3] == 4096 * 130) {
        RD=0; RT=1; RI=2; M1D=3; M1T=4; M1I=5; M2D=6; M2T=7; M2I=8;
        WQ=9; BQ=10; WK1=11; BK1=12; WV1=13; BV1=14; WK2=15; BK2=16; WV2=17; BV2=18; LT1=19; LT2=20;
    } else {
        RD=0; RT=1; M1D=2; M1T=3; M2D=4; M2T=5;
        WQ=6; BQ=7; WK1=8; BK1=9; WV1=10; BV1=11; WK2=12; BK2=13; WV2=14; BV2=15;
        LT1=16; LT2=17; RI=18; M1I=19; M2I=20;
    }

    k_setup<<<17, 256>>>(
        (const float*)d_in[WQ], (const float*)d_in[BQ],
        (const float*)d_in[WK1], (const float*)d_in[BK1],
        (const float*)d_in[WK2], (const float*)d_in[BK2],
        (const int*)d_in[M1I], (const int*)d_in[M2I]);

    k_pre<<<NQB + 256, 256>>>(
        (const float*)d_in[RD], (const float*)d_in[RT], (const int*)d_in[RI],
        (const float*)d_in[M1D], (const float*)d_in[M1T],
        (const float*)d_in[M2D], (const float*)d_in[M2T],
        (const float*)d_in[WV1], (const float*)d_in[BV1],
        (const float*)d_in[WV2], (const float*)d_in[BV2]);

    k_attn<<<dim3(128, 2, NCHUNK), 128>>>(
        (const float*)d_in[LT1], (const float*)d_in[LT2]);

    k_norm<<<(2 * T_Q * 32) / 256, 256>>>((float*)d_out);
}

// round 9
// speedup vs baseline: 1.0635x; 1.0375x over previous
#include <cuda_runtime.h>
#include <cuda_bf16.h>

#define T_Q 4096
#define L_KV 4096
#define LPAD (L_KV + 32)
#define NQB 64
#define NCHUNK 2

typedef unsigned long long ull;

// ---------------- scratch ----------------
__device__ float g_V[2][LPAD][128];
__device__ float g_kraw[2][LPAD];
__device__ float g_alpha[2][T_Q];
__device__ float g_beta[2][T_Q];
__device__ int   g_a[2][T_Q];
__device__ int   g_e[2][T_Q];
__device__ int   g_nc[2][T_Q];
__device__ float g_pacc[NCHUNK][2][T_Q][128];
__device__ float g_pden[NCHUNK][2][T_Q];
__device__ int   g_cnt[2][128];

// ---------------- helpers ----------------
__device__ __forceinline__ ull d_pk2(float a) {
    ull r; asm("mov.b64 %0, {%1, %1};" : "=l"(r) : "f"(a)); return r;
}
__device__ __forceinline__ ull d_fma2(ull a, ull b, ull c) {
    ull d; asm("fma.rn.f32x2 %0, %1, %2, %3;" : "=l"(d) : "l"(a), "l"(b), "l"(c)); return d;
}
__device__ __forceinline__ float2 d_up(ull v) {
    float2 f; asm("mov.b64 {%0, %1}, %2;" : "=f"(f.x), "=f"(f.y) : "l"(v)); return f;
}
__device__ __forceinline__ unsigned d_su32(const void* p) {
    unsigned r;
    asm("{ .reg .u64 t; cvta.to.shared.u64 t, %1; cvt.u32.u64 %0, t; }" : "=r"(r) : "l"(p));
    return r;
}

// ---------------- templated vproj core: 32 rows/CTA, warp owns 2 rows ----------------
template<int K, int SST>
__device__ __forceinline__ void vproj_core(const float* __restrict__ sm, int tid, int m, int rb,
                                           const float* __restrict__ Wv, const float* __restrict__ bv)
{
    int w = tid >> 5, lane = tid & 31;
    const ulonglong2* Wvp = (const ulonglong2*)Wv;
    float4 bias = ((const float4*)bv)[lane];
    const float* rbase = sm + (w * 2) * SST;

    ull a00 = 0ull, a01 = 0ull, a10 = 0ull, a11 = 0ull;

    #pragma unroll 8
    for (int i4 = 0; i4 < K / 4; i4++) {
        float4 r0 = *(const float4*)(rbase + i4 * 4);
        float4 r1 = *(const float4*)(rbase + SST + i4 * 4);
        #pragma unroll
        for (int ii = 0; ii < 4; ii++) {
            ulonglong2 wv = Wvp[(i4 * 4 + ii) * 32 + lane];
            float s0 = (ii == 0) ? r0.x : (ii == 1) ? r0.y : (ii == 2) ? r0.z : r0.w;
            float s1 = (ii == 0) ? r1.x : (ii == 1) ? r1.y : (ii == 2) ? r1.z : r1.w;
            ull p0 = d_pk2(s0), p1 = d_pk2(s1);
            a00 = d_fma2(p0, wv.x, a00); a01 = d_fma2(p0, wv.y, a01);
            a10 = d_fma2(p1, wv.x, a10); a11 = d_fma2(p1, wv.y, a11);
        }
    }

    int r0i = rb * 32 + w * 2;
    {
        float2 lo = d_up(a00), hi = d_up(a01);
        ((float4*)g_V[m][r0i])[lane] =
            make_float4(lo.x + bias.x, lo.y + bias.y, hi.x + bias.z, hi.y + bias.w);
    }
    {
        float2 lo = d_up(a10), hi = d_up(a11);
        ((float4*)g_V[m][r0i + 1])[lane] =
            make_float4(lo.x + bias.x, lo.y + bias.y, hi.x + bias.z, hi.y + bias.w);
    }
    if (lane < 2) g_kraw[m][r0i + lane] = sm[(w * 2 + lane) * SST + (K + 2) - 1];
}

// ---------------- kernel 1: qparams + vproj, 512-thread CTAs ----------------
// blocks [0, NQB): 64 queries each (alpha/beta/ranges, setup computed warp-parallel per CTA)
// blocks [NQB, NQB+256): V projection, 32 rows each; m = (b-NQB)>>7
__global__ void __launch_bounds__(512) k_pre(
    const float* __restrict__ ref_data, const float* __restrict__ ref_time,
    const int* __restrict__ ref_idx,
    const float* __restrict__ m1_data, const float* __restrict__ m1_time, const int* __restrict__ m1_idx,
    const float* __restrict__ m2_data, const float* __restrict__ m2_time, const int* __restrict__ m2_idx,
    const float* __restrict__ Wq, const float* __restrict__ bq,
    const float* __restrict__ Wk1, const float* __restrict__ bk1,
    const float* __restrict__ Wv1, const float* __restrict__ bv1,
    const float* __restrict__ Wk2, const float* __restrict__ bk2,
    const float* __restrict__ Wv2, const float* __restrict__ bv2)
{
    __shared__ __align__(16) float sm[4448];     // 17.8 KB, unioned
    int b = blockIdx.x;
    int tid = threadIdx.x;
    int warp = tid >> 5, lane = tid & 31;

    if (b < NQB) {
        // ---- qab path ----
        float* rbuf = sm;                 // [64][65]
        float* swA  = sm + 4160;          // [2][64]
        float* swB  = swA + 128;          // [2][64]
        float* scAB = swB + 128;          // [4]: cA0 cA1 cB0 cB1
        int*   slb  = (int*)(scAB + 4);   // [2][9]

        int t0 = b * 64;
        for (int i = tid; i < 64 * 64; i += 512) {
            int row = i >> 6, col = i & 63;
            rbuf[row * 65 + col] = ref_data[t0 * 64 + i];
        }

        // wA/wB: 128 outputs, 8 per warp, lane-split reductions
        #pragma unroll
        for (int oo = 0; oo < 8; oo++) {
            int o = warp * 8 + oo;        // 0..127
            int m = o >> 6, j = o & 63;
            const float* Wk = m ? Wk2 : Wk1;
            const float* bk = m ? bk2 : bk1;
            const float* wqrow = Wq + j * 128;
            float aA = 0.f, aB = 0.f;
            #pragma unroll
            for (int kk = 0; kk < 4; kk++) {
                int i = lane + 32 * kk;
                if (i < 127) {
                    float w = __ldg(wqrow + i + 1);
                    aA += w * __ldg(bk + i);
                    aB += w * __ldg(Wk + i);
                }
            }
            #pragma unroll
            for (int off = 16; off; off >>= 1) {
                aA += __shfl_xor_sync(0xffffffffu, aA, off);
                aB += __shfl_xor_sync(0xffffffffu, aB, off);
            }
            if (lane == 0) {
                swA[m * 64 + j] = __ldg(wqrow) - aA;
                swB[m * 64 + j] = aB;
            }
        }
        // cAB: warps 0-3, lane-split
        if (warp < 4) {
            int m = warp & 1; bool isB = warp >= 2;
            const float* Wk = m ? Wk2 : Wk1;
            const float* bk = m ? bk2 : bk1;
            const float* vec = isB ? Wk : bk;
            float acc = 0.f;
            #pragma unroll
            for (int kk = 0; kk < 4; kk++) {
                int i = lane + 32 * kk;
                if (i < 127) acc += __ldg(bq + i + 1) * __ldg(vec + i);
            }
            #pragma unroll
            for (int off = 16; off; off >>= 1)
                acc += __shfl_xor_sync(0xffffffffu, acc, off);
            if (lane == 0)
                scAB[warp] = isB ? (acc + __ldg(Wk + 127)) : (__ldg(bq) - acc - __ldg(bk + 127));
        }
        // idx lower bounds: warp 15, lanes 0-17
        if (warp == 15 && lane < 18) {
            int m = lane / 9, g = lane % 9;
            const int* midx = m ? m2_idx : m1_idx;
            int lo = 0, hi = L_KV;
            while (lo < hi) {
                int md = (lo + hi) >> 1;
                if (midx[md] < g) lo = md + 1; else hi = md;
            }
            slb[m * 9 + g] = lo;
        }
        __syncthreads();

        // phase B: one thread per (query, modality)
        if (tid < 128) {
            int m = tid >> 6, q = tid & 63;
            int t = t0 + q;
            float dA = 0.f, dB = 0.f;
            #pragma unroll 8
            for (int i = 0; i < 64; i++) {
                float r = rbuf[q * 65 + i];
                dA += r * swA[m * 64 + i];
                dB += r * swB[m * 64 + i];
            }
            g_alpha[m][t] = dA + scAB[m];
            g_beta[m][t]  = dB + scAB[2 + m];

            int id = ref_idx[t];
            float qt = ref_time[t];
            const float* mt = m ? m2_time : m1_time;
            int lo = 0, hi = L_KV;
            while (lo < hi) {
                int md = (lo + hi) >> 1;
                if (mt[md] <= qt) lo = md + 1; else hi = md;
            }
            int a = slb[m * 9 + id], bb = slb[m * 9 + id + 1];
            if (a == bb) { a = 0; bb = L_KV; }
            int e = min(bb, max(lo, a));
            g_a[m][t] = a; g_e[m][t] = e; g_nc[m][t] = bb - e;
        }
        return;
    }

    // ---- vproj path: 32 rows per CTA, 16 warps ----
    int vb = b - NQB;            // 0..255
    int m = vb >> 7;             // 0: m1, 1: m2
    int rb = vb & 127;           // row-block of 32
    int stride = m ? 66 : 130;
    int SST    = m ? 68 : 132;   // padded smem row stride (16B-aligned)
    const float* src = (m ? m2_data : m1_data) + rb * 32 * stride;

    // per-warp row staging (2 rows each), coalesced
    for (int r = warp; r < 32; r += 16)
        for (int c = lane; c < stride; c += 32)
            sm[r * SST + c] = src[r * stride + c];

    if (vb == 0) {   // zero V/kraw padding + combine counters once per launch
        float* gv = &g_V[0][0][0];
        for (int i = tid; i < 2 * 32 * 128; i += 512) {
            int mm = i / (32 * 128);
            int r  = i - mm * 32 * 128;
            gv[(mm * LPAD + L_KV) * 128 + r] = 0.f;
        }
        if (tid < 64) g_kraw[tid >> 5][L_KV + (tid & 31)] = 0.f;
        if (tid < 256) ((int*)g_cnt)[tid] = 0;
    }
    __syncthreads();

    if (m == 0) vproj_core<128, 132>(sm, tid, 0, rb, Wv1, bv1);
    else        vproj_core<64,  68>(sm, tid, 1, rb, Wv2, bv2);
}

// ---------------- kernel 2: attention + fused chunk combine ----------------
__global__ void __launch_bounds__(128) k_attn(const float* __restrict__ lt1,
                                              const float* __restrict__ lt2,
                                              float* __restrict__ out)
{
    int m = blockIdx.y, ch = blockIdx.z;
    int c = blockIdx.x;                              // 0..127
    int qb = (c & 1) ? (127 - (c >> 1)) : (c >> 1);  // front/back pairing for balance
    int tid = threadIdx.x;
    int warp = tid >> 5, lane = tid & 31;
    int t0c = qb * 32;

    __shared__ __align__(16) float buf[2][32 * 128];   // 32 KB
    __shared__ __align__(16) ull wsm[4][8][32];        // 8 KB
    __shared__ int s_c0[32], s_c1[32], s_b[2];
    __shared__ int s_last;

    if (tid < 32) {
        int t = t0c + tid;
        int a = g_a[m][t], e = g_e[m][t];
        int len = e - a;
        int c0 = a + ((len * ch) >> 1);
        int c1 = a + ((len * (ch + 1)) >> 1);
        s_c0[tid] = c0; s_c1[tid] = c1;
        int rmin = (c1 > c0) ? c0 : 0x7fffffff;
        int rmax = (c1 > c0) ? c1 : 0;
        #pragma unroll
        for (int off = 16; off; off >>= 1) {
            rmin = min(rmin, __shfl_xor_sync(0xffffffffu, rmin, off));
            rmax = max(rmax, __shfl_xor_sync(0xffffffffu, rmax, off));
        }
        if (tid == 0) { s_b[0] = rmin; s_b[1] = rmax; }
    }
    __syncthreads();
    int amin = s_b[0], emax = s_b[1];

    float nitau = -__expf(-(m ? *lt2 : *lt1));       // -1/tau
    int t0 = t0c + warp * 8;

    float alpha[8], nbeta[8], dpart[8];
    int aq[8], eq[8];
    ull alo[8], ahi[8];
    #pragma unroll
    for (int q = 0; q < 8; q++) {
        int t = t0 + q;
        alpha[q] = g_alpha[m][t]; nbeta[q] = -g_beta[m][t];
        aq[q] = s_c0[warp * 8 + q]; eq[q] = s_c1[warp * 8 + q];
        dpart[q] = 0.f; alo[q] = 0ull; ahi[q] = 0ull;
    }

    const float* gV = &g_V[m][0][0];
    const float* kr = g_kraw[m];
    ull* wme = &wsm[warp][0][0];
    unsigned sbuf0 = d_su32(&buf[0][0]);
    unsigned sbuf1 = d_su32(&buf[1][0]);

    int ntiles = (emax > amin) ? ((emax - amin + 31) >> 5) : 0;

    if (ntiles > 0) {
        {
            const float* g = gV + (size_t)amin * 128;
            #pragma unroll
            for (int i = 0; i < 8; i++) {
                int cid = i * 128 + tid;
                asm volatile("cp.async.cg.shared.global [%0], [%1], 16;"
                             :: "r"(sbuf0 + cid * 16), "l"(g + cid * 4) : "memory");
            }
            asm volatile("cp.async.commit_group;" ::: "memory");
        }
        int p = 0;
        for (int it = 0; it < ntiles; it++) {
            int l0 = amin + it * 32;
            asm volatile("cp.async.wait_group 0;" ::: "memory");
            __syncthreads();
            if (it + 1 < ntiles) {
                const float* g = gV + (size_t)(l0 + 32) * 128;
                unsigned sd = p ? sbuf0 : sbuf1;
                #pragma unroll
                for (int i = 0; i < 8; i++) {
                    int cid = i * 128 + tid;
                    asm volatile("cp.async.cg.shared.global [%0], [%1], 16;"
                                 :: "r"(sd + cid * 16), "l"(g + cid * 4) : "memory");
                }
            }
            asm volatile("cp.async.commit_group;" ::: "memory");

            int l = l0 + lane;
            float k = __ldg(kr + l);
            #pragma unroll
            for (int q = 0; q < 8; q++) {
                float s = fmaf(nbeta[q], k, alpha[q]);
                float w = (l >= aq[q] && l < eq[q]) ? __expf(s * s * nitau) : 0.f;
                wme[q * 32 + lane] = d_pk2(w);
                dpart[q] += w;
            }
            __syncwarp();

            const ulonglong2* bp = (const ulonglong2*)buf[p];
            #pragma unroll 8
            for (int j = 0; j < 32; j++) {
                ulonglong2 v = bp[j * 32 + lane];
                #pragma unroll
                for (int q = 0; q < 8; q++) {
                    ull wq = wme[q * 32 + j];
                    alo[q] = d_fma2(wq, v.x, alo[q]);
                    ahi[q] = d_fma2(wq, v.y, ahi[q]);
                }
            }
            p ^= 1;
        }
    }

    #pragma unroll
    for (int q = 0; q < 8; q++)
        #pragma unroll
        for (int off = 16; off; off >>= 1)
            dpart[q] += __shfl_xor_sync(0xffffffffu, dpart[q], off);

    // write partials
    float4* pa = (float4*)g_pacc[ch][m];
    #pragma unroll
    for (int q = 0; q < 8; q++) {
        float2 lo = d_up(alo[q]), hi = d_up(ahi[q]);
        pa[(t0 + q) * 32 + lane] = make_float4(lo.x, lo.y, hi.x, hi.y);
        if (lane == 0) g_pden[ch][m][t0 + q] = dpart[q];
    }

    // last CTA of the (m, qb) pair combines chunk0 + chunk1 (fixed order -> deterministic)
    __threadfence();
    __syncthreads();
    if (tid == 0) s_last = atomicAdd(&g_cnt[m][qb], 1);
    __syncthreads();
    if (s_last == 1) {
        const float4* p0 = (const float4*)g_pacc[0][m];
        const float4* p1 = (const float4*)g_pacc[1][m];
        float4* out4 = (float4*)out;
        #pragma unroll
        for (int q = 0; q < 8; q++) {
            int t = t0 + q;
            float den = g_pden[0][m][t] + g_pden[1][m][t] + (float)g_nc[m][t];
            float inv = 1.f / den;
            float4 a0 = p0[t * 32 + lane], a1 = p1[t * 32 + lane];
            out4[t * 64 + m * 32 + lane] =
                make_float4((a0.x + a1.x) * inv, (a0.y + a1.y) * inv,
                            (a0.z + a1.z) * inv, (a0.w + a1.w) * inv);
        }
    }
}

// ---------------- launch ----------------
extern "C" void kernel_launch(void* const* d_in, const int* in_sizes, int n_in,
                              void* d_out, int out_size)
{
    int RD, RT, RI, M1D, M1T, M1I, M2D, M2T, M2I, WQ, BQ, WK1, BK1, WV1, BV1, WK2, BK2, WV2, BV2, LT1, LT2;
    if (in_sizes[3] == 4096 * 130) {
        RD=0; RT=1; RI=2; M1D=3; M1T=4; M1I=5; M2D=6; M2T=7; M2I=8;
        WQ=9; BQ=10; WK1=11; BK1=12; WV1=13; BV1=14; WK2=15; BK2=16; WV2=17; BV2=18; LT1=19; LT2=20;
    } else {
        RD=0; RT=1; M1D=2; M1T=3; M2D=4; M2T=5;
        WQ=6; BQ=7; WK1=8; BK1=9; WV1=10; BV1=11; WK2=12; BK2=13; WV2=14; BV2=15;
        LT1=16; LT2=17; RI=18; M1I=19; M2I=20;
    }

    k_pre<<<NQB + 256, 512>>>(
        (const float*)d_in[RD], (const float*)d_in[RT], (const int*)d_in[RI],
        (const float*)d_in[M1D], (const float*)d_in[M1T], (const int*)d_in[M1I],
        (const float*)d_in[M2D], (const float*)d_in[M2T], (const int*)d_in[M2I],
        (const float*)d_in[WQ], (const float*)d_in[BQ],
        (const float*)d_in[WK1], (const float*)d_in[BK1],
        (const float*)d_in[WV1], (const float*)d_in[BV1],
        (const float*)d_in[WK2], (const float*)d_in[BK2],
        (const float*)d_in[WV2], (const float*)d_in[BV2]);

    k_attn<<<dim3(128, 2, NCHUNK), 128>>>(
        (const float*)d_in[LT1], (const float*)d_in[LT2], (float*)d_out);
}